// round 13
// baseline (speedup 1.0000x reference)
#include <cuda_runtime.h>
#include <cstdint>

// IF spiking neuron, T=4. 128 MiB in + 128 MiB out (compulsory).
// R13: last untried mechanism — TMA bulk stores. Spikes staged in SMEM
// (32KB/CTA), then one elected thread issues 4x cp.async.bulk (1D, S2G,
// 8KB contiguous per timestep slab). Writes reach DRAM as long monolithic
// bursts through the TMA engine instead of per-warp STG packets interleaved
// with reads -> fewer read/write turnarounds at the memory controller.
// Read path unchanged from champion: 4 independent LDG.E.256 per thread.

#define TSTEPS 4
#define THREADS 256
#define SLAB_BYTES (THREADS * 32)   // 8192 bytes per slab per CTA

struct __align__(32) f8 { float v[8]; };

__device__ __forceinline__ f8 ldg256(const f8* p) {
    f8 r;
    asm volatile("ld.global.v8.f32 {%0,%1,%2,%3,%4,%5,%6,%7}, [%8];"
                 : "=f"(r.v[0]), "=f"(r.v[1]), "=f"(r.v[2]), "=f"(r.v[3]),
                   "=f"(r.v[4]), "=f"(r.v[5]), "=f"(r.v[6]), "=f"(r.v[7])
                 : "l"(p));
    return r;
}

__global__ __launch_bounds__(THREADS)
void if_kernel(const f8* __restrict__ x,
               const float* __restrict__ thresh,
               f8* __restrict__ out,
               int stride8)
{
    __shared__ __align__(128) f8 smem[TSTEPS][THREADS];

    int tid = threadIdx.x;
    int i = blockIdx.x * THREADS + tid;

    const float th = __ldg(thresh);
    const float m0 = 0.5f * th;

    // 4 independent strided 32B loads (128B in flight per thread).
    f8 xt[TSTEPS];
#pragma unroll
    for (int t = 0; t < TSTEPS; t++)
        xt[t] = ldg256(&x[i + t * stride8]);

    // In-place membrane recurrence: 8 independent scalar chains.
#pragma unroll
    for (int c = 0; c < 8; c++) {
        float m = m0;
#pragma unroll
        for (int t = 0; t < TSTEPS; t++) {
            m += xt[t].v[c];
            float s = (m >= th) ? th : 0.0f;
            xt[t].v[c] = s;
            m -= s;
        }
    }

    // Stage spikes in SMEM (STS is issue-only).
#pragma unroll
    for (int t = 0; t < TSTEPS; t++)
        smem[t][tid] = xt[t];

    __syncthreads();

    // Make generic-proxy SMEM writes visible to the async (TMA) proxy.
    asm volatile("fence.proxy.async.shared::cta;" ::: "memory");

    // One thread issues 4 contiguous 8KB bulk writes (one per slab).
    if (tid == 0) {
        uint32_t sbase;
        asm("{ .reg .u64 t; cvta.to.shared.u64 t, %1; cvt.u32.u64 %0, t; }"
            : "=r"(sbase) : "l"(&smem[0][0]));
#pragma unroll
        for (int t = 0; t < TSTEPS; t++) {
            const f8* gdst = &out[blockIdx.x * THREADS + t * stride8];
            asm volatile(
                "cp.async.bulk.global.shared::cta.bulk_group [%0], [%1], %2;"
                :: "l"(gdst), "r"(sbase + t * SLAB_BYTES), "n"(SLAB_BYTES)
                : "memory");
        }
        asm volatile("cp.async.bulk.commit_group;" ::: "memory");
        // Drain before CTA exit (SMEM must stay live until reads complete).
        asm volatile("cp.async.bulk.wait_group.read 0;" ::: "memory");
    }
}

extern "C" void kernel_launch(void* const* d_in, const int* in_sizes, int n_in,
                              void* d_out, int out_size)
{
    const float* x      = (const float*)d_in[0];
    const float* thresh = (const float*)d_in[1];
    float* out          = (float*)d_out;

    int n = in_sizes[0];              // total elements = 2^27
    int stride = n / TSTEPS;          // elements per timestep slab = 8388608
    int stride8 = stride / 8;         // f8 units per slab = 1048576

    int blocks = stride8 / THREADS;   // 4096, exact
    if_kernel<<<blocks, THREADS>>>(
        (const f8*)x, thresh, (f8*)out, stride8);
}

// round 14
// speedup vs baseline: 1.0057x; 1.0057x over previous
#include <cuda_runtime.h>

// IF spiking neuron, T=4. FINAL champion (R8 config, reproduced 3x).
// x:[T*B,C,H,W] fp32; per position: mem=0.5*th; for t: mem+=x[t];
// s=(mem>=th)?th:0; out[t]=s; mem-=s. Bit-exact fp32 order vs reference.
//
// 128 MiB in + 128 MiB out; both streams exceed the 126MB L2 -> 268MB DRAM
// traffic is compulsory and wall = traffic / BW_eff = 43.5us @ 6.16 TB/s,
// the measured mixed read/write HBM3e plateau (~77% of 8TB/s spec).
// Closed axes: MLP(4/8), vector width(128/256b), block(256/512/1024),
// persistent vs saturating grid, full cache-policy matrix, STG vs TMA bulk
// stores. Compute pipes <10%, issue 13% -> purely HBM-bound, saturated.
//
// Structure: one thread = one 32B lane across the 4 timestep slabs.
// 4 independent LDG.E.256 batched up-front (128B in flight per thread),
// in-register membrane recurrence (8 independent scalar chains), 4 STG.E.256.
// 512 threads/block, 2048 blocks (exact), 48 regs.

#define TSTEPS 4

struct __align__(32) f8 { float v[8]; };

__device__ __forceinline__ f8 ldg256(const f8* p) {
    f8 r;
    asm volatile("ld.global.v8.f32 {%0,%1,%2,%3,%4,%5,%6,%7}, [%8];"
                 : "=f"(r.v[0]), "=f"(r.v[1]), "=f"(r.v[2]), "=f"(r.v[3]),
                   "=f"(r.v[4]), "=f"(r.v[5]), "=f"(r.v[6]), "=f"(r.v[7])
                 : "l"(p));
    return r;
}

__device__ __forceinline__ void stg256(f8* p, const f8& r) {
    asm volatile("st.global.v8.f32 [%0], {%1,%2,%3,%4,%5,%6,%7,%8};"
                 :: "l"(p),
                    "f"(r.v[0]), "f"(r.v[1]), "f"(r.v[2]), "f"(r.v[3]),
                    "f"(r.v[4]), "f"(r.v[5]), "f"(r.v[6]), "f"(r.v[7])
                 : "memory");
}

__global__ __launch_bounds__(512)
void if_kernel(const f8* __restrict__ x,
               const float* __restrict__ thresh,
               f8* __restrict__ out,
               int stride8)
{
    int i = blockIdx.x * blockDim.x + threadIdx.x;

    const float th = __ldg(thresh);
    const float m0 = 0.5f * th;

    // 4 independent strided 32B loads (128B in flight per thread).
    f8 xt[TSTEPS];
#pragma unroll
    for (int t = 0; t < TSTEPS; t++)
        xt[t] = ldg256(&x[i + t * stride8]);

    // In-place membrane recurrence: 8 independent scalar chains.
#pragma unroll
    for (int c = 0; c < 8; c++) {
        float m = m0;
#pragma unroll
        for (int t = 0; t < TSTEPS; t++) {
            m += xt[t].v[c];
            float s = (m >= th) ? th : 0.0f;
            xt[t].v[c] = s;
            m -= s;
        }
    }

#pragma unroll
    for (int t = 0; t < TSTEPS; t++)
        stg256(&out[i + t * stride8], xt[t]);
}

extern "C" void kernel_launch(void* const* d_in, const int* in_sizes, int n_in,
                              void* d_out, int out_size)
{
    const float* x      = (const float*)d_in[0];
    const float* thresh = (const float*)d_in[1];
    float* out          = (float*)d_out;

    int n = in_sizes[0];              // total elements = 2^27
    int stride = n / TSTEPS;          // elements per timestep slab = 8388608
    int stride8 = stride / 8;         // f8 units per slab = 1048576

    int threads = 512;
    int blocks = stride8 / threads;   // 2048, exact
    if_kernel<<<blocks, threads>>>(
        (const f8*)x, thresh, (f8*)out, stride8);
}